// round 14
// baseline (speedup 1.0000x reference)
#include <cuda_runtime.h>
#include <cuda_bf16.h>
#include <cstdint>

#define N_NODES 50000
#define E_EDGES 800000
#define K_TOT   256     // concat K (mean 128 | self 128) for every layer
#define SCAN_BLOCKS ((N_NODES + 1023) / 1024)   // 49

// ---------------- device scratch (no allocs allowed) ----------------
__device__ int   g_deg[N_NODES];
__device__ int   g_rowptr[N_NODES + 1];
__device__ int   g_cursor[N_NODES];
__device__ int   g_col[E_EDGES];
__device__ int   g_bsum[SCAN_BLOCKS];
__device__ __align__(16) __nv_bfloat16 g_Ahi[(size_t)N_NODES * K_TOT];  // [N,256]: cols 0-127 mean, 128-255 self
__device__ __align__(16) __nv_bfloat16 g_Alo[(size_t)N_NODES * K_TOT];
__device__ __align__(16) __nv_bfloat16 g_BhiA[3 * 256 * K_TOT];         // per-layer [Do,256] weight hi
__device__ __align__(16) __nv_bfloat16 g_BloA[3 * 256 * K_TOT];         // per-layer weight lo

// ---------------- helpers ----------------
__device__ __forceinline__ uint32_t smem_u32(const void* p) {
    uint32_t a;
    asm("{ .reg .u64 t; cvta.to.shared.u64 t, %1; cvt.u32.u64 %0, t; }" : "=r"(a) : "l"(p));
    return a;
}
__device__ __forceinline__ void cp16(void* sdst, const void* gsrc, int szr) {
    uint32_t d = smem_u32(sdst);
    asm volatile("cp.async.cg.shared.global [%0], [%1], 16, %2;" :: "r"(d), "l"(gsrc), "r"(szr) : "memory");
}
#define CP_COMMIT() asm volatile("cp.async.commit_group;" ::: "memory")
#define CP_WAIT1()  asm volatile("cp.async.wait_group 1;" ::: "memory")
#define CP_WAIT0()  asm volatile("cp.async.wait_group 0;" ::: "memory")
#define LDSM_X4(R0, R1, R2, R3, a) \
    asm volatile("ldmatrix.sync.aligned.m8n8.x4.shared.b16 {%0,%1,%2,%3}, [%4];" \
                 : "=r"(R0), "=r"(R1), "=r"(R2), "=r"(R3) : "r"(a))

// ---------------- CSR build ----------------
__global__ void k_zero_deg() {
    int i = blockIdx.x * blockDim.x + threadIdx.x;
    if (i < N_NODES) g_deg[i] = 0;
}
__global__ void k_count(const int* __restrict__ ei) {
    int e = blockIdx.x * blockDim.x + threadIdx.x;
    if (e < E_EDGES) {
        int d = ei[E_EDGES + e];
        if (d >= 0 && d < N_NODES) atomicAdd(&g_deg[d], 1);
    }
}
__global__ void k_scan_part() {
    __shared__ int wsum[32];
    int t = threadIdx.x, lane = t & 31, wd = t >> 5;
    int i = blockIdx.x * 1024 + t;
    int v = (i < N_NODES) ? g_deg[i] : 0;
    int s = v;
    #pragma unroll
    for (int o = 1; o < 32; o <<= 1) {
        int n = __shfl_up_sync(0xffffffffu, s, o);
        if (lane >= o) s += n;
    }
    if (lane == 31) wsum[wd] = s;
    __syncthreads();
    if (wd == 0) {
        int w = wsum[lane];
        #pragma unroll
        for (int o = 1; o < 32; o <<= 1) {
            int n = __shfl_up_sync(0xffffffffu, w, o);
            if (lane >= o) w += n;
        }
        wsum[lane] = w;
    }
    __syncthreads();
    int excl_local = (wd ? wsum[wd - 1] : 0) + s - v;
    if (i < N_NODES) g_rowptr[i] = excl_local;
    if (t == 1023) g_bsum[blockIdx.x] = (wd ? wsum[wd - 1] : 0) + s;
}
__global__ void k_scan_add() {
    __shared__ int base_s;
    int t = threadIdx.x;
    if (t == 0) {
        int b = 0;
        #pragma unroll 1
        for (int j = 0; j < (int)blockIdx.x; j++) b += g_bsum[j];
        base_s = b;
    }
    __syncthreads();
    int i = blockIdx.x * 1024 + t;
    if (i < N_NODES) {
        int v = g_rowptr[i] + base_s;
        g_rowptr[i] = v;
        g_cursor[i] = v;
    }
    if (blockIdx.x == SCAN_BLOCKS - 1 && t == 0)
        g_rowptr[N_NODES] = base_s + g_bsum[SCAN_BLOCKS - 1];
}
__global__ void k_fill(const int* __restrict__ ei) {
    int e = blockIdx.x * blockDim.x + threadIdx.x;
    if (e < E_EDGES) {
        int s = ei[e];
        int d = ei[E_EDGES + e];
        if (d >= 0 && d < N_NODES && s >= 0 && s < N_NODES) {
            int p = atomicAdd(&g_cursor[d], 1);
            g_col[p] = s;
        }
    }
}

// ---------------- weight prep, all 3 layers in one launch ----------------
__global__ void k_prep_all(const float* __restrict__ Wl0, const float* __restrict__ Wr0,
                           const float* __restrict__ Wl1, const float* __restrict__ Wr1,
                           const float* __restrict__ Wl2, const float* __restrict__ Wr2) {
    int idx = blockIdx.x * blockDim.x + threadIdx.x;
    if (idx >= 3 * 256 * K_TOT) return;
    int layer = idx >> 16;
    int rem = idx & 65535;
    int j = rem >> 8, k = rem & 255;
    int Do = (layer == 2) ? 256 : 128;
    if (j >= Do) return;
    const float* Wl = (layer == 0) ? Wl0 : (layer == 1) ? Wl1 : Wl2;
    const float* Wr = (layer == 0) ? Wr0 : (layer == 1) ? Wr1 : Wr2;
    float v = (k < 128) ? Wl[j * 128 + k] : Wr[j * 128 + (k - 128)];
    __nv_bfloat16 hi = __float2bfloat16_rn(v);
    float lo = v - __bfloat162float(hi);
    g_BhiA[idx] = hi;
    g_BloA[idx] = __float2bfloat16_rn(lo);
}

// ---------------- split store helper ----------------
__device__ __forceinline__ void store_split(size_t off, float4 v) {
    __nv_bfloat16 h0 = __float2bfloat16_rn(v.x), h1 = __float2bfloat16_rn(v.y);
    __nv_bfloat16 h2 = __float2bfloat16_rn(v.z), h3 = __float2bfloat16_rn(v.w);
    __nv_bfloat162 a; a.x = h0; a.y = h1;
    __nv_bfloat162 b; b.x = h2; b.y = h3;
    *(__nv_bfloat162*)(g_Ahi + off)     = a;
    *(__nv_bfloat162*)(g_Ahi + off + 2) = b;
    __nv_bfloat162 la, lb;
    la.x = __float2bfloat16_rn(v.x - __bfloat162float(h0));
    la.y = __float2bfloat16_rn(v.y - __bfloat162float(h1));
    lb.x = __float2bfloat16_rn(v.z - __bfloat162float(h2));
    lb.y = __float2bfloat16_rn(v.w - __bfloat162float(h3));
    *(__nv_bfloat162*)(g_Alo + off)     = la;
    *(__nv_bfloat162*)(g_Alo + off + 2) = lb;
}

// seed layer-0 self columns from x
__global__ void k_self0(const float* __restrict__ x) {
    int idx = blockIdx.x * blockDim.x + threadIdx.x;   // over 50000*32
    if (idx >= N_NODES * 32) return;
    int node = idx >> 5, lane = idx & 31;
    float4 v = ((const float4*)x)[(size_t)node * 32 + lane];
    store_split((size_t)node * K_TOT + 128 + 4 * lane, v);
}

// ---------------- aggregation: warp/node gather-mean (mean cols only) ----------------
__global__ void k_agg(const float* __restrict__ x_ext, int sel) {
    int node = blockIdx.x * (blockDim.x >> 5) + (threadIdx.x >> 5);
    int lane = threadIdx.x & 31;
    if (node >= N_NODES) return;
    int beg = g_rowptr[node], end = g_rowptr[node + 1];

    float4 a0 = {0.f, 0.f, 0.f, 0.f};
    float4 a1 = {0.f, 0.f, 0.f, 0.f};

    if (sel == 0) {
        const float4* x4 = (const float4*)x_ext;
        int e = beg;
        for (; e + 1 < end; e += 2) {
            int s0 = g_col[e], s1 = g_col[e + 1];
            float4 v0 = x4[(size_t)s0 * 32 + lane];
            float4 v1 = x4[(size_t)s1 * 32 + lane];
            a0.x += v0.x; a0.y += v0.y; a0.z += v0.z; a0.w += v0.w;
            a1.x += v1.x; a1.y += v1.y; a1.z += v1.z; a1.w += v1.w;
        }
        if (e < end) {
            int s0 = g_col[e];
            float4 v0 = x4[(size_t)s0 * 32 + lane];
            a0.x += v0.x; a0.y += v0.y; a0.z += v0.z; a0.w += v0.w;
        }
    } else {
        // gather hi/lo split pairs from self cols (128..255): uint2 = 4 bf16 per lane
        const uint2* Hi = (const uint2*)g_Ahi;
        const uint2* Lo = (const uint2*)g_Alo;
        int e = beg;
        for (; e + 1 < end; e += 2) {
            int s0 = g_col[e], s1 = g_col[e + 1];
            uint2 h0 = Hi[(size_t)s0 * 64 + 32 + lane];
            uint2 l0 = Lo[(size_t)s0 * 64 + 32 + lane];
            uint2 h1 = Hi[(size_t)s1 * 64 + 32 + lane];
            uint2 l1 = Lo[(size_t)s1 * 64 + 32 + lane];
            float2 ha = __bfloat1622float2(*(__nv_bfloat162*)&h0.x);
            float2 hb = __bfloat1622float2(*(__nv_bfloat162*)&h0.y);
            float2 la = __bfloat1622float2(*(__nv_bfloat162*)&l0.x);
            float2 lb = __bfloat1622float2(*(__nv_bfloat162*)&l0.y);
            a0.x += ha.x + la.x; a0.y += ha.y + la.y;
            a0.z += hb.x + lb.x; a0.w += hb.y + lb.y;
            ha = __bfloat1622float2(*(__nv_bfloat162*)&h1.x);
            hb = __bfloat1622float2(*(__nv_bfloat162*)&h1.y);
            la = __bfloat1622float2(*(__nv_bfloat162*)&l1.x);
            lb = __bfloat1622float2(*(__nv_bfloat162*)&l1.y);
            a1.x += ha.x + la.x; a1.y += ha.y + la.y;
            a1.z += hb.x + lb.x; a1.w += hb.y + lb.y;
        }
        if (e < end) {
            int s0 = g_col[e];
            uint2 h0 = Hi[(size_t)s0 * 64 + 32 + lane];
            uint2 l0 = Lo[(size_t)s0 * 64 + 32 + lane];
            float2 ha = __bfloat1622float2(*(__nv_bfloat162*)&h0.x);
            float2 hb = __bfloat1622float2(*(__nv_bfloat162*)&h0.y);
            float2 la = __bfloat1622float2(*(__nv_bfloat162*)&l0.x);
            float2 lb = __bfloat1622float2(*(__nv_bfloat162*)&l0.y);
            a0.x += ha.x + la.x; a0.y += ha.y + la.y;
            a0.z += hb.x + lb.x; a0.w += hb.y + lb.y;
        }
    }

    int cnt = end - beg;
    float inv = 1.0f / (float)(cnt > 0 ? cnt : 1);
    float4 m;
    m.x = (a0.x + a1.x) * inv;
    m.y = (a0.y + a1.y) * inv;
    m.z = (a0.z + a1.z) * inv;
    m.w = (a0.w + a1.w) * inv;
    store_split((size_t)node * K_TOT + 4 * lane, m);        // mean cols 0..127
}

// ---------------- mma.sync bf16 helper ----------------
__device__ __forceinline__ void mma16816(float* c, uint32_t a0, uint32_t a1, uint32_t a2, uint32_t a3,
                                         uint32_t b0, uint32_t b1) {
    asm volatile("mma.sync.aligned.m16n8k16.row.col.f32.bf16.bf16.f32 "
                 "{%0,%1,%2,%3}, {%4,%5,%6,%7}, {%8,%9}, {%0,%1,%2,%3};"
                 : "+f"(c[0]), "+f"(c[1]), "+f"(c[2]), "+f"(c[3])
                 : "r"(a0), "r"(a1), "r"(a2), "r"(a3), "r"(b0), "r"(b1));
}

// ---------------- double-buffered tensor-core GEMM (LDSM frag loads) ----------------
// BM=128, BN=128, 512 threads: 16 warps as 4(M) x 4(N), warp tile 32x32.
// D += Ahi*Bhi + Ahi*Blo + Alo*Bhi  (fp32 accum in registers)
#define S_STRIDE 72                    // bf16 elems per SMEM row (144B)
#define ROW_B    (S_STRIDE * 2)        // 144 bytes
#define BUF_ELEMS (4 * 128 * S_STRIDE)

template<int DO, bool RELU, bool WSPLIT>
__global__ __launch_bounds__(512) void k_gemm_db(const float* __restrict__ bias,
                                                 float* __restrict__ Cext, int layer) {
    extern __shared__ __nv_bfloat16 sm[];
    const int tid = threadIdx.x;
    const int wid = tid >> 5, lane = tid & 31;
    const int warp_m = wid & 3, warp_n = wid >> 2;    // 4 x 4
    const int g = lane >> 2, tg = lane & 3;
    const int block_m = blockIdx.x * 128;
    const int block_n = blockIdx.y * 128;
    const size_t woff = (size_t)layer * 8192;         // layer offset in uint4 units

    // LDSM lane-derived byte offsets
    const int aoff = (((lane >> 3) & 1) * 8 + (lane & 7)) * ROW_B + (lane >> 4) * 16;
    const int boff = (((lane >> 4) & 1) * 8 + (lane & 7)) * ROW_B + ((lane >> 3) & 1) * 16;

    auto stage = [&](int ch, int b) {
        __nv_bfloat16* As_hi = sm + b * BUF_ELEMS;
        __nv_bfloat16* As_lo = As_hi + 128 * S_STRIDE;
        __nv_bfloat16* Bs_hi = As_lo + 128 * S_STRIDE;
        __nv_bfloat16* Bs_lo = Bs_hi + 128 * S_STRIDE;
        const int k8 = ch * 8;
        #pragma unroll
        for (int it = 0; it < 2; it++) {
            int idx = tid + it * 512;
            int r = idx >> 3, c8 = idx & 7;
            int row = block_m + r;
            int sz = (row < N_NODES) ? 16 : 0;
            int rowc = (row < N_NODES) ? row : (N_NODES - 1);
            size_t gi = (size_t)rowc * 32 + k8 + c8;
            cp16(As_hi + r * S_STRIDE + c8 * 8, (const char*)g_Ahi + gi * 16, sz);
            cp16(As_lo + r * S_STRIDE + c8 * 8, (const char*)g_Alo + gi * 16, sz);
        }
        #pragma unroll
        for (int it = 0; it < 2; it++) {
            int idx = tid + it * 512;
            int r = idx >> 3, c8 = idx & 7;
            size_t gi = woff + (size_t)(block_n + r) * 32 + k8 + c8;
            cp16(Bs_hi + r * S_STRIDE + c8 * 8, (const char*)g_BhiA + gi * 16, 16);
            cp16(Bs_lo + r * S_STRIDE + c8 * 8, (const char*)g_BloA + gi * 16, 16);
        }
        CP_COMMIT();
    };

    float acc[2][4][4];
    #pragma unroll
    for (int mi = 0; mi < 2; mi++)
        #pragma unroll
        for (int ni = 0; ni < 4; ni++)
            #pragma unroll
            for (int j = 0; j < 4; j++) acc[mi][ni][j] = 0.f;

    stage(0, 0);

    for (int ch = 0; ch < 4; ch++) {
        if (ch < 3) stage(ch + 1, (ch + 1) & 1);
        if (ch < 3) { CP_WAIT1(); } else { CP_WAIT0(); }
        __syncthreads();

        const uint32_t sbase = smem_u32(sm + (ch & 1) * BUF_ELEMS);
        const uint32_t sAhi = sbase + warp_m * 32 * ROW_B + aoff;
        const uint32_t sAlo = sAhi + 128 * ROW_B;
        const uint32_t sBhi = sbase + 256 * ROW_B + warp_n * 32 * ROW_B + boff;
        const uint32_t sBlo = sBhi + 128 * ROW_B;

        #pragma unroll
        for (int ks = 0; ks < 4; ks++) {
            const int kb = ks * 32;     // byte offset of k0 within row
            uint32_t ah[2][4], al[2][4], bh2[2][4], bl2[2][4];
            #pragma unroll
            for (int mi = 0; mi < 2; mi++) {
                LDSM_X4(ah[mi][0], ah[mi][1], ah[mi][2], ah[mi][3], sAhi + mi * 16 * ROW_B + kb);
                LDSM_X4(al[mi][0], al[mi][1], al[mi][2], al[mi][3], sAlo + mi * 16 * ROW_B + kb);
            }
            #pragma unroll
            for (int p = 0; p < 2; p++) {
                LDSM_X4(bh2[p][0], bh2[p][1], bh2[p][2], bh2[p][3], sBhi + p * 16 * ROW_B + kb);
                LDSM_X4(bl2[p][0], bl2[p][1], bl2[p][2], bl2[p][3], sBlo + p * 16 * ROW_B + kb);
            }
            #pragma unroll
            for (int mi = 0; mi < 2; mi++)
                #pragma unroll
                for (int ni = 0; ni < 4; ni++) {
                    const int p = ni >> 1, q = ni & 1;
                    mma16816(acc[mi][ni], ah[mi][0], ah[mi][1], ah[mi][2], ah[mi][3],
                             bh2[p][q * 2], bh2[p][q * 2 + 1]);
                    mma16816(acc[mi][ni], ah[mi][0], ah[mi][1], ah[mi][2], ah[mi][3],
                             bl2[p][q * 2], bl2[p][q * 2 + 1]);
                    mma16816(acc[mi][ni], al[mi][0], al[mi][1], al[mi][2], al[mi][3],
                             bh2[p][q * 2], bh2[p][q * 2 + 1]);
                }
        }
        __syncthreads();
    }

    // epilogue: either write fp32 C (layer 2) or hi/lo split into self cols of g_A*
    #pragma unroll
    for (int mi = 0; mi < 2; mi++) {
        #pragma unroll
        for (int ni = 0; ni < 4; ni++) {
            int col = block_n + warp_n * 32 + ni * 8 + tg * 2;
            float bx = bias[col], by = bias[col + 1];
            int row0 = block_m + warp_m * 32 + mi * 16 + g;
            #pragma unroll
            for (int h = 0; h < 2; h++) {
                int row = row0 + h * 8;
                if (row < N_NODES) {
                    float vx = acc[mi][ni][h * 2 + 0] + bx;
                    float vy = acc[mi][ni][h * 2 + 1] + by;
                    if (RELU) { vx = fmaxf(vx, 0.f); vy = fmaxf(vy, 0.f); }
                    if (WSPLIT) {
                        __nv_bfloat16 hx = __float2bfloat16_rn(vx);
                        __nv_bfloat16 hy = __float2bfloat16_rn(vy);
                        __nv_bfloat162 hv; hv.x = hx; hv.y = hy;
                        __nv_bfloat162 lv;
                        lv.x = __float2bfloat16_rn(vx - __bfloat162float(hx));
                        lv.y = __float2bfloat16_rn(vy - __bfloat162float(hy));
                        size_t off = (size_t)row * K_TOT + 128 + col;
                        *(__nv_bfloat162*)(g_Ahi + off) = hv;
                        *(__nv_bfloat162*)(g_Alo + off) = lv;
                    } else {
                        float2 o = {vx, vy};
                        *(float2*)&Cext[(size_t)row * DO + col] = o;
                    }
                }
            }
        }
    }
}

extern "C" void kernel_launch(void* const* d_in, const int* in_sizes, int n_in,
                              void* d_out, int out_size) {
    const float* x   = (const float*)d_in[0];
    const int*   ei  = (const int*)d_in[1];
    const float* Wl0 = (const float*)d_in[2];
    const float* bl0 = (const float*)d_in[3];
    const float* Wr0 = (const float*)d_in[4];
    const float* Wl1 = (const float*)d_in[5];
    const float* bl1 = (const float*)d_in[6];
    const float* Wr1 = (const float*)d_in[7];
    const float* Wl2 = (const float*)d_in[8];
    const float* bl2 = (const float*)d_in[9];
    const float* Wr2 = (const float*)d_in[10];
    float* out = (float*)d_out;

    const int SMEM = 2 * BUF_ELEMS * 2;   // 147456 B
    cudaFuncSetAttribute(k_gemm_db<128, true, true>,   cudaFuncAttributeMaxDynamicSharedMemorySize, SMEM);
    cudaFuncSetAttribute(k_gemm_db<256, false, false>, cudaFuncAttributeMaxDynamicSharedMemorySize, SMEM);

    // --- CSR build + weight prep + layer-0 self split ---
    k_zero_deg<<<(N_NODES + 255) / 256, 256>>>();
    k_count<<<(E_EDGES + 255) / 256, 256>>>(ei);
    k_prep_all<<<(3 * 256 * K_TOT + 255) / 256, 256>>>(Wl0, Wr0, Wl1, Wr1, Wl2, Wr2);
    k_self0<<<(N_NODES * 32 + 255) / 256, 256>>>(x);
    k_scan_part<<<SCAN_BLOCKS, 1024>>>();
    k_scan_add<<<SCAN_BLOCKS, 1024>>>();
    k_fill<<<(E_EDGES + 255) / 256, 256>>>(ei);

    const int GRID_M = (N_NODES + 127) / 128;   // 391

    // --- layer 0 ---
    k_agg<<<(N_NODES + 7) / 8, 256>>>(x, 0);
    k_gemm_db<128, true, true><<<dim3(GRID_M, 1), 512, SMEM>>>(bl0, nullptr, 0);

    // --- layer 1 ---
    k_agg<<<(N_NODES + 7) / 8, 256>>>(nullptr, 1);
    k_gemm_db<128, true, true><<<dim3(GRID_M, 1), 512, SMEM>>>(bl1, nullptr, 1);

    // --- layer 2 ---
    k_agg<<<(N_NODES + 7) / 8, 256>>>(nullptr, 2);
    k_gemm_db<256, false, false><<<dim3(GRID_M, 2), 512, SMEM>>>(bl2, out, 2);
}

// round 16
// speedup vs baseline: 1.0219x; 1.0219x over previous
#include <cuda_runtime.h>
#include <cuda_bf16.h>
#include <cstdint>

#define N_NODES 50000
#define E_EDGES 800000
#define K_TOT   256     // concat K (mean 128 | self 128) for every layer
#define SCAN_BLOCKS ((N_NODES + 1023) / 1024)   // 49
#define COUNT_BLOCKS ((E_EDGES + 255) / 256)    // 3125
#define PREP_BLOCKS  ((3 * 256 * K_TOT + 255) / 256)   // 768

// ---------------- device scratch (no allocs allowed) ----------------
__device__ int   g_deg[N_NODES];
__device__ int   g_rowptr[N_NODES + 1];
__device__ int   g_cursor[N_NODES];
__device__ int   g_col[E_EDGES];
__device__ int   g_bsum[SCAN_BLOCKS];
__device__ __align__(16) __nv_bfloat16 g_Ahi[(size_t)N_NODES * K_TOT];  // [N,256] hi split of [mean|h]
__device__ __align__(16) __nv_bfloat16 g_Alo[(size_t)N_NODES * K_TOT];  // [N,256] lo split
__device__ __align__(16) __nv_bfloat16 g_BhiA[3 * 256 * K_TOT];         // per-layer [Do,256] weight hi
__device__ __align__(16) __nv_bfloat16 g_BloA[3 * 256 * K_TOT];         // per-layer weight lo
__device__ __align__(16) float g_h0[(size_t)N_NODES * 128];
__device__ __align__(16) float g_h1[(size_t)N_NODES * 128];

// ---------------- helpers ----------------
__device__ __forceinline__ uint32_t smem_u32(const void* p) {
    uint32_t a;
    asm("{ .reg .u64 t; cvta.to.shared.u64 t, %1; cvt.u32.u64 %0, t; }" : "=r"(a) : "l"(p));
    return a;
}
__device__ __forceinline__ void cp16(void* sdst, const void* gsrc, int szr) {
    uint32_t d = smem_u32(sdst);
    asm volatile("cp.async.cg.shared.global [%0], [%1], 16, %2;" :: "r"(d), "l"(gsrc), "r"(szr) : "memory");
}
#define CP_COMMIT() asm volatile("cp.async.commit_group;" ::: "memory")
#define CP_WAIT1()  asm volatile("cp.async.wait_group 1;" ::: "memory")
#define CP_WAIT0()  asm volatile("cp.async.wait_group 0;" ::: "memory")

// ---------------- CSR build ----------------
__global__ void k_zero_deg() {
    int i = blockIdx.x * blockDim.x + threadIdx.x;
    if (i < N_NODES) g_deg[i] = 0;
}

// merged: edge-degree count (blocks [0, COUNT_BLOCKS)) + weight hi/lo prep (rest)
__global__ void k_count_prep(const int* __restrict__ ei,
                             const float* __restrict__ Wl0, const float* __restrict__ Wr0,
                             const float* __restrict__ Wl1, const float* __restrict__ Wr1,
                             const float* __restrict__ Wl2, const float* __restrict__ Wr2) {
    if (blockIdx.x < COUNT_BLOCKS) {
        int e = blockIdx.x * blockDim.x + threadIdx.x;
        if (e < E_EDGES) {
            int d = ei[E_EDGES + e];
            if (d >= 0 && d < N_NODES) atomicAdd(&g_deg[d], 1);
        }
    } else {
        int idx = (blockIdx.x - COUNT_BLOCKS) * blockDim.x + threadIdx.x;
        if (idx >= 3 * 256 * K_TOT) return;
        int layer = idx >> 16;
        int rem = idx & 65535;
        int j = rem >> 8, k = rem & 255;
        int Do = (layer == 2) ? 256 : 128;
        if (j >= Do) return;
        const float* Wl = (layer == 0) ? Wl0 : (layer == 1) ? Wl1 : Wl2;
        const float* Wr = (layer == 0) ? Wr0 : (layer == 1) ? Wr1 : Wr2;
        float v = (k < 128) ? Wl[j * 128 + k] : Wr[j * 128 + (k - 128)];
        __nv_bfloat16 hi = __float2bfloat16_rn(v);
        float lo = v - __bfloat162float(hi);
        g_BhiA[idx] = hi;
        g_BloA[idx] = __float2bfloat16_rn(lo);
    }
}

__global__ void k_scan_part() {
    __shared__ int wsum[32];
    int t = threadIdx.x, lane = t & 31, wd = t >> 5;
    int i = blockIdx.x * 1024 + t;
    int v = (i < N_NODES) ? g_deg[i] : 0;
    int s = v;
    #pragma unroll
    for (int o = 1; o < 32; o <<= 1) {
        int n = __shfl_up_sync(0xffffffffu, s, o);
        if (lane >= o) s += n;
    }
    if (lane == 31) wsum[wd] = s;
    __syncthreads();
    if (wd == 0) {
        int w = wsum[lane];
        #pragma unroll
        for (int o = 1; o < 32; o <<= 1) {
            int n = __shfl_up_sync(0xffffffffu, w, o);
            if (lane >= o) w += n;
        }
        wsum[lane] = w;
    }
    __syncthreads();
    int excl_local = (wd ? wsum[wd - 1] : 0) + s - v;
    if (i < N_NODES) g_rowptr[i] = excl_local;
    if (t == 1023) g_bsum[blockIdx.x] = (wd ? wsum[wd - 1] : 0) + s;
}
__global__ void k_scan_add() {
    __shared__ int base_s;
    int t = threadIdx.x;
    if (t == 0) {
        int b = 0;
        #pragma unroll 1
        for (int j = 0; j < (int)blockIdx.x; j++) b += g_bsum[j];
        base_s = b;
    }
    __syncthreads();
    int i = blockIdx.x * 1024 + t;
    if (i < N_NODES) {
        int v = g_rowptr[i] + base_s;
        g_rowptr[i] = v;
        g_cursor[i] = v;
    }
    if (blockIdx.x == SCAN_BLOCKS - 1 && t == 0)
        g_rowptr[N_NODES] = base_s + g_bsum[SCAN_BLOCKS - 1];
}
// 2 edges per thread via int2 (E even)
__global__ void k_fill(const int* __restrict__ ei) {
    int p2 = blockIdx.x * blockDim.x + threadIdx.x;
    if (p2 * 2 >= E_EDGES) return;
    int2 s2 = ((const int2*)ei)[p2];
    int2 d2 = ((const int2*)(ei + E_EDGES))[p2];
    if (d2.x >= 0 && d2.x < N_NODES && s2.x >= 0 && s2.x < N_NODES) {
        int p = atomicAdd(&g_cursor[d2.x], 1);
        g_col[p] = s2.x;
    }
    if (d2.y >= 0 && d2.y < N_NODES && s2.y >= 0 && s2.y < N_NODES) {
        int p = atomicAdd(&g_cursor[d2.y], 1);
        g_col[p] = s2.y;
    }
}

// ---------------- split store helper ----------------
__device__ __forceinline__ void store_split(size_t off, float4 v) {
    __nv_bfloat16 h0 = __float2bfloat16_rn(v.x), h1 = __float2bfloat16_rn(v.y);
    __nv_bfloat16 h2 = __float2bfloat16_rn(v.z), h3 = __float2bfloat16_rn(v.w);
    __nv_bfloat162 a; a.x = h0; a.y = h1;
    __nv_bfloat162 b; b.x = h2; b.y = h3;
    *(__nv_bfloat162*)(g_Ahi + off)     = a;
    *(__nv_bfloat162*)(g_Ahi + off + 2) = b;
    __nv_bfloat162 la, lb;
    la.x = __float2bfloat16_rn(v.x - __bfloat162float(h0));
    la.y = __float2bfloat16_rn(v.y - __bfloat162float(h1));
    lb.x = __float2bfloat16_rn(v.z - __bfloat162float(h2));
    lb.y = __float2bfloat16_rn(v.w - __bfloat162float(h3));
    *(__nv_bfloat162*)(g_Alo + off)     = la;
    *(__nv_bfloat162*)(g_Alo + off + 2) = lb;
}

// ---------------- aggregation: warp/node gather-mean, 4-way unrolled ----------------
__global__ void k_agg(const float* __restrict__ x_ext, int sel) {
    const float* xin = (sel == 0) ? x_ext : (sel == 1) ? g_h0 : g_h1;
    int node = blockIdx.x * (blockDim.x >> 5) + (threadIdx.x >> 5);
    int lane = threadIdx.x & 31;
    if (node >= N_NODES) return;
    int beg = g_rowptr[node], end = g_rowptr[node + 1];
    const float4* x4 = (const float4*)xin;

    float4 a0 = {0.f, 0.f, 0.f, 0.f};
    float4 a1 = {0.f, 0.f, 0.f, 0.f};
    float4 a2 = {0.f, 0.f, 0.f, 0.f};
    float4 a3 = {0.f, 0.f, 0.f, 0.f};
    int e = beg;
    for (; e + 3 < end; e += 4) {
        int s0 = g_col[e], s1 = g_col[e + 1], s2 = g_col[e + 2], s3 = g_col[e + 3];
        float4 v0 = x4[(size_t)s0 * 32 + lane];
        float4 v1 = x4[(size_t)s1 * 32 + lane];
        float4 v2 = x4[(size_t)s2 * 32 + lane];
        float4 v3 = x4[(size_t)s3 * 32 + lane];
        a0.x += v0.x; a0.y += v0.y; a0.z += v0.z; a0.w += v0.w;
        a1.x += v1.x; a1.y += v1.y; a1.z += v1.z; a1.w += v1.w;
        a2.x += v2.x; a2.y += v2.y; a2.z += v2.z; a2.w += v2.w;
        a3.x += v3.x; a3.y += v3.y; a3.z += v3.z; a3.w += v3.w;
    }
    for (; e < end; e++) {
        int s0 = g_col[e];
        float4 v0 = x4[(size_t)s0 * 32 + lane];
        a0.x += v0.x; a0.y += v0.y; a0.z += v0.z; a0.w += v0.w;
    }
    int cnt = end - beg;
    float inv = 1.0f / (float)(cnt > 0 ? cnt : 1);
    float4 m;
    m.x = (a0.x + a1.x + a2.x + a3.x) * inv;
    m.y = (a0.y + a1.y + a2.y + a3.y) * inv;
    m.z = (a0.z + a1.z + a2.z + a3.z) * inv;
    m.w = (a0.w + a1.w + a2.w + a3.w) * inv;

    size_t base = (size_t)node * K_TOT + 4 * lane;
    store_split(base, m);                                   // cols 0..127: mean
    store_split(base + 128, x4[(size_t)node * 32 + lane]);  // cols 128..255: self
}

// ---------------- mma.sync bf16 helper ----------------
__device__ __forceinline__ void mma16816(float* c, uint32_t a0, uint32_t a1, uint32_t a2, uint32_t a3,
                                         uint32_t b0, uint32_t b1) {
    asm volatile("mma.sync.aligned.m16n8k16.row.col.f32.bf16.bf16.f32 "
                 "{%0,%1,%2,%3}, {%4,%5,%6,%7}, {%8,%9}, {%0,%1,%2,%3};"
                 : "+f"(c[0]), "+f"(c[1]), "+f"(c[2]), "+f"(c[3])
                 : "r"(a0), "r"(a1), "r"(a2), "r"(a3), "r"(b0), "r"(b1));
}

// ---------------- double-buffered tensor-core GEMM ----------------
// BM=128, BN=128, 512 threads: 16 warps as 4(M) x 4(N), warp tile 32x32.
// K staged in 4 chunks of 64 via cp.async, 2-deep pipeline.
// D += Ahi*Bhi + Ahi*Blo + Alo*Bhi  (fp32 accum in registers)
#define S_STRIDE 72                    // bf16 elems per SMEM row (144B)
#define BUF_ELEMS (4 * 128 * S_STRIDE) // As_hi, As_lo, Bs_hi, Bs_lo each 128 rows

template<int DO, bool RELU>
__global__ __launch_bounds__(512) void k_gemm_db(const float* __restrict__ bias,
                                                 float* __restrict__ Cext, int csel, int layer) {
    extern __shared__ __nv_bfloat16 sm[];
    float* C = (csel == 0) ? g_h0 : (csel == 1) ? g_h1 : Cext;
    const int tid = threadIdx.x;
    const int wid = tid >> 5, lane = tid & 31;
    const int warp_m = wid & 3, warp_n = wid >> 2;    // 4 x 4
    const int g = lane >> 2, tg = lane & 3;
    const int block_m = blockIdx.x * 128;
    const int block_n = blockIdx.y * 128;
    const size_t woff = (size_t)layer * 8192;         // layer offset in uint4 units

    auto stage = [&](int ch, int b) {
        __nv_bfloat16* As_hi = sm + b * BUF_ELEMS;
        __nv_bfloat16* As_lo = As_hi + 128 * S_STRIDE;
        __nv_bfloat16* Bs_hi = As_lo + 128 * S_STRIDE;
        __nv_bfloat16* Bs_lo = Bs_hi + 128 * S_STRIDE;
        const int k8 = ch * 8;
        #pragma unroll
        for (int it = 0; it < 2; it++) {
            int idx = tid + it * 512;
            int r = idx >> 3, c8 = idx & 7;
            int row = block_m + r;
            int sz = (row < N_NODES) ? 16 : 0;
            int rowc = (row < N_NODES) ? row : (N_NODES - 1);
            size_t gi = (size_t)rowc * 32 + k8 + c8;
            cp16(As_hi + r * S_STRIDE + c8 * 8, (const char*)g_Ahi + gi * 16, sz);
            cp16(As_lo + r * S_STRIDE + c8 * 8, (const char*)g_Alo + gi * 16, sz);
        }
        #pragma unroll
        for (int it = 0; it < 2; it++) {
            int idx = tid + it * 512;
            int r = idx >> 3, c8 = idx & 7;
            size_t gi = woff + (size_t)(block_n + r) * 32 + k8 + c8;
            cp16(Bs_hi + r * S_STRIDE + c8 * 8, (const char*)g_BhiA + gi * 16, 16);
            cp16(Bs_lo + r * S_STRIDE + c8 * 8, (const char*)g_BloA + gi * 16, 16);
        }
        CP_COMMIT();
    };

    float acc[2][4][4];
    #pragma unroll
    for (int mi = 0; mi < 2; mi++)
        #pragma unroll
        for (int ni = 0; ni < 4; ni++)
            #pragma unroll
            for (int j = 0; j < 4; j++) acc[mi][ni][j] = 0.f;

    stage(0, 0);

    for (int ch = 0; ch < 4; ch++) {
        if (ch < 3) stage(ch + 1, (ch + 1) & 1);
        if (ch < 3) { CP_WAIT1(); } else { CP_WAIT0(); }
        __syncthreads();

        const __nv_bfloat16* base = sm + (ch & 1) * BUF_ELEMS;
        const __nv_bfloat16* As_hi = base;
        const __nv_bfloat16* As_lo = base + 128 * S_STRIDE;
        const __nv_bfloat16* Bs_hi = base + 256 * S_STRIDE;
        const __nv_bfloat16* Bs_lo = base + 384 * S_STRIDE;

        #pragma unroll
        for (int ks = 0; ks < 4; ks++) {
            const int k0 = ks * 16;
            uint32_t ah[2][4], al[2][4];
            #pragma unroll
            for (int mi = 0; mi < 2; mi++) {
                int r0 = warp_m * 32 + mi * 16 + g;
                const __nv_bfloat16* ph0 = As_hi + r0 * S_STRIDE + k0 + tg * 2;
                const __nv_bfloat16* ph1 = As_hi + (r0 + 8) * S_STRIDE + k0 + tg * 2;
                ah[mi][0] = *(const uint32_t*)ph0;
                ah[mi][1] = *(const uint32_t*)ph1;
                ah[mi][2] = *(const uint32_t*)(ph0 + 8);
                ah[mi][3] = *(const uint32_t*)(ph1 + 8);
                const __nv_bfloat16* pl0 = As_lo + r0 * S_STRIDE + k0 + tg * 2;
                const __nv_bfloat16* pl1 = As_lo + (r0 + 8) * S_STRIDE + k0 + tg * 2;
                al[mi][0] = *(const uint32_t*)pl0;
                al[mi][1] = *(const uint32_t*)pl1;
                al[mi][2] = *(const uint32_t*)(pl0 + 8);
                al[mi][3] = *(const uint32_t*)(pl1 + 8);
            }
            uint32_t bh[4][2], bl[4][2];
            #pragma unroll
            for (int ni = 0; ni < 4; ni++) {
                int n0 = warp_n * 32 + ni * 8 + g;
                const __nv_bfloat16* qh = Bs_hi + n0 * S_STRIDE + k0 + tg * 2;
                bh[ni][0] = *(const uint32_t*)qh;
                bh[ni][1] = *(const uint32_t*)(qh + 8);
                const __nv_bfloat16* ql = Bs_lo + n0 * S_STRIDE + k0 + tg * 2;
                bl[ni][0] = *(const uint32_t*)ql;
                bl[ni][1] = *(const uint32_t*)(ql + 8);
            }
            #pragma unroll
            for (int mi = 0; mi < 2; mi++)
                #pragma unroll
                for (int ni = 0; ni < 4; ni++) {
                    mma16816(acc[mi][ni], ah[mi][0], ah[mi][1], ah[mi][2], ah[mi][3], bh[ni][0], bh[ni][1]);
                    mma16816(acc[mi][ni], ah[mi][0], ah[mi][1], ah[mi][2], ah[mi][3], bl[ni][0], bl[ni][1]);
                    mma16816(acc[mi][ni], al[mi][0], al[mi][1], al[mi][2], al[mi][3], bh[ni][0], bh[ni][1]);
                }
        }
        __syncthreads();
    }

    // epilogue
    #pragma unroll
    for (int mi = 0; mi < 2; mi++) {
        #pragma unroll
        for (int ni = 0; ni < 4; ni++) {
            int col = block_n + warp_n * 32 + ni * 8 + tg * 2;
            float bx = bias[col], by = bias[col + 1];
            int row0 = block_m + warp_m * 32 + mi * 16 + g;
            #pragma unroll
            for (int h = 0; h < 2; h++) {
                int row = row0 + h * 8;
                if (row < N_NODES) {
                    float vx = acc[mi][ni][h * 2 + 0] + bx;
                    float vy = acc[mi][ni][h * 2 + 1] + by;
                    if (RELU) { vx = fmaxf(vx, 0.f); vy = fmaxf(vy, 0.f); }
                    float2 o = {vx, vy};
                    *(float2*)&C[(size_t)row * DO + col] = o;
                }
            }
        }
    }
}

extern "C" void kernel_launch(void* const* d_in, const int* in_sizes, int n_in,
                              void* d_out, int out_size) {
    const float* x   = (const float*)d_in[0];
    const int*   ei  = (const int*)d_in[1];     // int32 (harness converts int64)
    const float* Wl0 = (const float*)d_in[2];
    const float* bl0 = (const float*)d_in[3];
    const float* Wr0 = (const float*)d_in[4];
    const float* Wl1 = (const float*)d_in[5];
    const float* bl1 = (const float*)d_in[6];
    const float* Wr1 = (const float*)d_in[7];
    const float* Wl2 = (const float*)d_in[8];
    const float* bl2 = (const float*)d_in[9];
    const float* Wr2 = (const float*)d_in[10];
    float* out = (float*)d_out;

    const int SMEM = 2 * BUF_ELEMS * 2;   // 147456 B
    cudaFuncSetAttribute(k_gemm_db<128, true>,  cudaFuncAttributeMaxDynamicSharedMemorySize, SMEM);
    cudaFuncSetAttribute(k_gemm_db<256, false>, cudaFuncAttributeMaxDynamicSharedMemorySize, SMEM);

    // --- CSR build + weight prep ---
    k_zero_deg<<<(N_NODES + 255) / 256, 256>>>();
    k_count_prep<<<COUNT_BLOCKS + PREP_BLOCKS, 256>>>(ei, Wl0, Wr0, Wl1, Wr1, Wl2, Wr2);
    k_scan_part<<<SCAN_BLOCKS, 1024>>>();
    k_scan_add<<<SCAN_BLOCKS, 1024>>>();
    k_fill<<<(E_EDGES / 2 + 255) / 256, 256>>>(ei);

    const int GRID_M = (N_NODES + 127) / 128;   // 391

    // --- layer 0: x -> g_h0 (relu) ---
    k_agg<<<(N_NODES + 7) / 8, 256>>>(x, 0);
    k_gemm_db<128, true><<<dim3(GRID_M, 1), 512, SMEM>>>(bl0, nullptr, 0, 0);

    // --- layer 1: g_h0 -> g_h1 (relu) ---
    k_agg<<<(N_NODES + 7) / 8, 256>>>(nullptr, 1);
    k_gemm_db<128, true><<<dim3(GRID_M, 1), 512, SMEM>>>(bl1, nullptr, 1, 1);

    // --- layer 2: g_h1 -> out (no relu) ---
    k_agg<<<(N_NODES + 7) / 8, 256>>>(nullptr, 2);
    k_gemm_db<256, false><<<dim3(GRID_M, 2), 512, SMEM>>>(bl2, out, 2, 2);
}

// round 17
// speedup vs baseline: 1.0870x; 1.0638x over previous
#include <cuda_runtime.h>
#include <cuda_bf16.h>
#include <cstdint>

#define N_NODES 50000
#define E_EDGES 800000
#define K_TOT   256     // concat K (mean 128 | self 128) for every layer
#define SCAN_BLOCKS ((N_NODES + 1023) / 1024)   // 49
#define COUNT_BLOCKS ((E_EDGES + 255) / 256)    // 3125
#define PREP_BLOCKS  ((3 * 256 * K_TOT + 255) / 256)   // 768

// ---------------- device scratch (no allocs allowed) ----------------
__device__ int   g_deg[N_NODES];
__device__ int   g_rowptr[N_NODES + 1];
__device__ int   g_cursor[N_NODES];
__device__ int   g_col[E_EDGES];
__device__ int   g_bsum[SCAN_BLOCKS];
__device__ __align__(16) __nv_bfloat16 g_Ahi[(size_t)N_NODES * K_TOT];  // [N,256] hi split of [mean|h]
__device__ __align__(16) __nv_bfloat16 g_Alo[(size_t)N_NODES * K_TOT];  // [N,256] lo split
__device__ __align__(16) __nv_bfloat16 g_BhiA[3 * 256 * K_TOT];         // per-layer [Do,256] weight hi
__device__ __align__(16) __nv_bfloat16 g_BloA[3 * 256 * K_TOT];         // per-layer weight lo
__device__ __align__(16) float g_h0[(size_t)N_NODES * 128];
__device__ __align__(16) float g_h1[(size_t)N_NODES * 128];

// ---------------- helpers ----------------
__device__ __forceinline__ uint32_t smem_u32(const void* p) {
    uint32_t a;
    asm("{ .reg .u64 t; cvta.to.shared.u64 t, %1; cvt.u32.u64 %0, t; }" : "=r"(a) : "l"(p));
    return a;
}
__device__ __forceinline__ void cp16(void* sdst, const void* gsrc, int szr) {
    uint32_t d = smem_u32(sdst);
    asm volatile("cp.async.cg.shared.global [%0], [%1], 16, %2;" :: "r"(d), "l"(gsrc), "r"(szr) : "memory");
}
#define CP_COMMIT() asm volatile("cp.async.commit_group;" ::: "memory")
#define CP_WAIT1()  asm volatile("cp.async.wait_group 1;" ::: "memory")
#define CP_WAIT0()  asm volatile("cp.async.wait_group 0;" ::: "memory")

// ---------------- CSR build ----------------
__global__ void k_zero_deg() {
    int i = blockIdx.x * blockDim.x + threadIdx.x;
    if (i < N_NODES) g_deg[i] = 0;
}

// merged: edge-degree count (blocks [0, COUNT_BLOCKS)) + weight hi/lo prep (rest)
__global__ void k_count_prep(const int* __restrict__ ei,
                             const float* __restrict__ Wl0, const float* __restrict__ Wr0,
                             const float* __restrict__ Wl1, const float* __restrict__ Wr1,
                             const float* __restrict__ Wl2, const float* __restrict__ Wr2) {
    if (blockIdx.x < COUNT_BLOCKS) {
        int e = blockIdx.x * blockDim.x + threadIdx.x;
        if (e < E_EDGES) {
            int d = ei[E_EDGES + e];
            if (d >= 0 && d < N_NODES) atomicAdd(&g_deg[d], 1);
        }
    } else {
        int idx = (blockIdx.x - COUNT_BLOCKS) * blockDim.x + threadIdx.x;
        if (idx >= 3 * 256 * K_TOT) return;
        int layer = idx >> 16;
        int rem = idx & 65535;
        int j = rem >> 8, k = rem & 255;
        int Do = (layer == 2) ? 256 : 128;
        if (j >= Do) return;
        const float* Wl = (layer == 0) ? Wl0 : (layer == 1) ? Wl1 : Wl2;
        const float* Wr = (layer == 0) ? Wr0 : (layer == 1) ? Wr1 : Wr2;
        float v = (k < 128) ? Wl[j * 128 + k] : Wr[j * 128 + (k - 128)];
        __nv_bfloat16 hi = __float2bfloat16_rn(v);
        float lo = v - __bfloat162float(hi);
        g_BhiA[idx] = hi;
        g_BloA[idx] = __float2bfloat16_rn(lo);
    }
}

__global__ void k_scan_part() {
    __shared__ int wsum[32];
    int t = threadIdx.x, lane = t & 31, wd = t >> 5;
    int i = blockIdx.x * 1024 + t;
    int v = (i < N_NODES) ? g_deg[i] : 0;
    int s = v;
    #pragma unroll
    for (int o = 1; o < 32; o <<= 1) {
        int n = __shfl_up_sync(0xffffffffu, s, o);
        if (lane >= o) s += n;
    }
    if (lane == 31) wsum[wd] = s;
    __syncthreads();
    if (wd == 0) {
        int w = wsum[lane];
        #pragma unroll
        for (int o = 1; o < 32; o <<= 1) {
            int n = __shfl_up_sync(0xffffffffu, w, o);
            if (lane >= o) w += n;
        }
        wsum[lane] = w;
    }
    __syncthreads();
    int excl_local = (wd ? wsum[wd - 1] : 0) + s - v;
    if (i < N_NODES) g_rowptr[i] = excl_local;
    if (t == 1023) g_bsum[blockIdx.x] = (wd ? wsum[wd - 1] : 0) + s;
}
__global__ void k_scan_add() {
    __shared__ int base_s;
    int t = threadIdx.x;
    if (t == 0) {
        int b = 0;
        #pragma unroll 1
        for (int j = 0; j < (int)blockIdx.x; j++) b += g_bsum[j];
        base_s = b;
    }
    __syncthreads();
    int i = blockIdx.x * 1024 + t;
    if (i < N_NODES) {
        int v = g_rowptr[i] + base_s;
        g_rowptr[i] = v;
        g_cursor[i] = v;
    }
    if (blockIdx.x == SCAN_BLOCKS - 1 && t == 0)
        g_rowptr[N_NODES] = base_s + g_bsum[SCAN_BLOCKS - 1];
}
__global__ void k_fill(const int* __restrict__ ei) {
    int e = blockIdx.x * blockDim.x + threadIdx.x;
    if (e < E_EDGES) {
        int s = ei[e];
        int d = ei[E_EDGES + e];
        if (d >= 0 && d < N_NODES && s >= 0 && s < N_NODES) {
            int p = atomicAdd(&g_cursor[d], 1);
            g_col[p] = s;
        }
    }
}

// ---------------- split store helper ----------------
__device__ __forceinline__ void store_split(size_t off, float4 v) {
    __nv_bfloat16 h0 = __float2bfloat16_rn(v.x), h1 = __float2bfloat16_rn(v.y);
    __nv_bfloat16 h2 = __float2bfloat16_rn(v.z), h3 = __float2bfloat16_rn(v.w);
    __nv_bfloat162 a; a.x = h0; a.y = h1;
    __nv_bfloat162 b; b.x = h2; b.y = h3;
    *(__nv_bfloat162*)(g_Ahi + off)     = a;
    *(__nv_bfloat162*)(g_Ahi + off + 2) = b;
    __nv_bfloat162 la, lb;
    la.x = __float2bfloat16_rn(v.x - __bfloat162float(h0));
    la.y = __float2bfloat16_rn(v.y - __bfloat162float(h1));
    lb.x = __float2bfloat16_rn(v.z - __bfloat162float(h2));
    lb.y = __float2bfloat16_rn(v.w - __bfloat162float(h3));
    *(__nv_bfloat162*)(g_Alo + off)     = la;
    *(__nv_bfloat162*)(g_Alo + off + 2) = lb;
}

// ---------------- aggregation: warp/node gather-mean (2-way unroll, R13-exact) ----------------
__global__ void k_agg(const float* __restrict__ x_ext, int sel) {
    const float* xin = (sel == 0) ? x_ext : (sel == 1) ? g_h0 : g_h1;
    int node = blockIdx.x * (blockDim.x >> 5) + (threadIdx.x >> 5);
    int lane = threadIdx.x & 31;
    if (node >= N_NODES) return;
    int beg = g_rowptr[node], end = g_rowptr[node + 1];
    const float4* x4 = (const float4*)xin;

    float4 a0 = {0.f, 0.f, 0.f, 0.f};
    float4 a1 = {0.f, 0.f, 0.f, 0.f};
    int e = beg;
    for (; e + 1 < end; e += 2) {
        int s0 = g_col[e], s1 = g_col[e + 1];
        float4 v0 = x4[(size_t)s0 * 32 + lane];
        float4 v1 = x4[(size_t)s1 * 32 + lane];
        a0.x += v0.x; a0.y += v0.y; a0.z += v0.z; a0.w += v0.w;
        a1.x += v1.x; a1.y += v1.y; a1.z += v1.z; a1.w += v1.w;
    }
    if (e < end) {
        int s0 = g_col[e];
        float4 v0 = x4[(size_t)s0 * 32 + lane];
        a0.x += v0.x; a0.y += v0.y; a0.z += v0.z; a0.w += v0.w;
    }
    int cnt = end - beg;
    float inv = 1.0f / (float)(cnt > 0 ? cnt : 1);
    float4 m;
    m.x = (a0.x + a1.x) * inv;
    m.y = (a0.y + a1.y) * inv;
    m.z = (a0.z + a1.z) * inv;
    m.w = (a0.w + a1.w) * inv;

    size_t base = (size_t)node * K_TOT + 4 * lane;
    store_split(base, m);                                   // cols 0..127: mean
    store_split(base + 128, x4[(size_t)node * 32 + lane]);  // cols 128..255: self
}

// ---------------- mma.sync bf16 helper ----------------
__device__ __forceinline__ void mma16816(float* c, uint32_t a0, uint32_t a1, uint32_t a2, uint32_t a3,
                                         uint32_t b0, uint32_t b1) {
    asm volatile("mma.sync.aligned.m16n8k16.row.col.f32.bf16.bf16.f32 "
                 "{%0,%1,%2,%3}, {%4,%5,%6,%7}, {%8,%9}, {%0,%1,%2,%3};"
                 : "+f"(c[0]), "+f"(c[1]), "+f"(c[2]), "+f"(c[3])
                 : "r"(a0), "r"(a1), "r"(a2), "r"(a3), "r"(b0), "r"(b1));
}

// ---------------- double-buffered tensor-core GEMM ----------------
// BM=128, BN=128, 512 threads: 16 warps as 4(M) x 4(N), warp tile 32x32.
// K staged in 4 chunks of 64 via cp.async, 2-deep pipeline.
// D += Ahi*Bhi + Ahi*Blo + Alo*Bhi  (fp32 accum in registers)
#define S_STRIDE 72                    // bf16 elems per SMEM row (144B)
#define BUF_ELEMS (4 * 128 * S_STRIDE) // As_hi, As_lo, Bs_hi, Bs_lo each 128 rows

template<int DO, bool RELU>
__global__ __launch_bounds__(512) void k_gemm_db(const float* __restrict__ bias,
                                                 float* __restrict__ Cext, int csel, int layer) {
    extern __shared__ __nv_bfloat16 sm[];
    float* C = (csel == 0) ? g_h0 : (csel == 1) ? g_h1 : Cext;
    const int tid = threadIdx.x;
    const int wid = tid >> 5, lane = tid & 31;
    const int warp_m = wid & 3, warp_n = wid >> 2;    // 4 x 4
    const int g = lane >> 2, tg = lane & 3;
    const int block_m = blockIdx.x * 128;
    const int block_n = blockIdx.y * 128;
    const size_t woff = (size_t)layer * 8192;         // layer offset in uint4 units

    auto stage = [&](int ch, int b) {
        __nv_bfloat16* As_hi = sm + b * BUF_ELEMS;
        __nv_bfloat16* As_lo = As_hi + 128 * S_STRIDE;
        __nv_bfloat16* Bs_hi = As_lo + 128 * S_STRIDE;
        __nv_bfloat16* Bs_lo = Bs_hi + 128 * S_STRIDE;
        const int k8 = ch * 8;
        #pragma unroll
        for (int it = 0; it < 2; it++) {
            int idx = tid + it * 512;
            int r = idx >> 3, c8 = idx & 7;
            int row = block_m + r;
            int sz = (row < N_NODES) ? 16 : 0;
            int rowc = (row < N_NODES) ? row : (N_NODES - 1);
            size_t gi = (size_t)rowc * 32 + k8 + c8;
            cp16(As_hi + r * S_STRIDE + c8 * 8, (const char*)g_Ahi + gi * 16, sz);
            cp16(As_lo + r * S_STRIDE + c8 * 8, (const char*)g_Alo + gi * 16, sz);
        }
        #pragma unroll
        for (int it = 0; it < 2; it++) {
            int idx = tid + it * 512;
            int r = idx >> 3, c8 = idx & 7;
            size_t gi = woff + (size_t)(block_n + r) * 32 + k8 + c8;
            cp16(Bs_hi + r * S_STRIDE + c8 * 8, (const char*)g_BhiA + gi * 16, 16);
            cp16(Bs_lo + r * S_STRIDE + c8 * 8, (const char*)g_BloA + gi * 16, 16);
        }
        CP_COMMIT();
    };

    float acc[2][4][4];
    #pragma unroll
    for (int mi = 0; mi < 2; mi++)
        #pragma unroll
        for (int ni = 0; ni < 4; ni++)
            #pragma unroll
            for (int j = 0; j < 4; j++) acc[mi][ni][j] = 0.f;

    stage(0, 0);

    for (int ch = 0; ch < 4; ch++) {
        if (ch < 3) stage(ch + 1, (ch + 1) & 1);
        if (ch < 3) { CP_WAIT1(); } else { CP_WAIT0(); }
        __syncthreads();

        const __nv_bfloat16* base = sm + (ch & 1) * BUF_ELEMS;
        const __nv_bfloat16* As_hi = base;
        const __nv_bfloat16* As_lo = base + 128 * S_STRIDE;
        const __nv_bfloat16* Bs_hi = base + 256 * S_STRIDE;
        const __nv_bfloat16* Bs_lo = base + 384 * S_STRIDE;

        #pragma unroll
        for (int ks = 0; ks < 4; ks++) {
            const int k0 = ks * 16;
            uint32_t ah[2][4], al[2][4];
            #pragma unroll
            for (int mi = 0; mi < 2; mi++) {
                int r0 = warp_m * 32 + mi * 16 + g;
                const __nv_bfloat16* ph0 = As_hi + r0 * S_STRIDE + k0 + tg * 2;
                const __nv_bfloat16* ph1 = As_hi + (r0 + 8) * S_STRIDE + k0 + tg * 2;
                ah[mi][0] = *(const uint32_t*)ph0;
                ah[mi][1] = *(const uint32_t*)ph1;
                ah[mi][2] = *(const uint32_t*)(ph0 + 8);
                ah[mi][3] = *(const uint32_t*)(ph1 + 8);
                const __nv_bfloat16* pl0 = As_lo + r0 * S_STRIDE + k0 + tg * 2;
                const __nv_bfloat16* pl1 = As_lo + (r0 + 8) * S_STRIDE + k0 + tg * 2;
                al[mi][0] = *(const uint32_t*)pl0;
                al[mi][1] = *(const uint32_t*)pl1;
                al[mi][2] = *(const uint32_t*)(pl0 + 8);
                al[mi][3] = *(const uint32_t*)(pl1 + 8);
            }
            uint32_t bh[4][2], bl[4][2];
            #pragma unroll
            for (int ni = 0; ni < 4; ni++) {
                int n0 = warp_n * 32 + ni * 8 + g;
                const __nv_bfloat16* qh = Bs_hi + n0 * S_STRIDE + k0 + tg * 2;
                bh[ni][0] = *(const uint32_t*)qh;
                bh[ni][1] = *(const uint32_t*)(qh + 8);
                const __nv_bfloat16* ql = Bs_lo + n0 * S_STRIDE + k0 + tg * 2;
                bl[ni][0] = *(const uint32_t*)ql;
                bl[ni][1] = *(const uint32_t*)(ql + 8);
            }
            #pragma unroll
            for (int mi = 0; mi < 2; mi++)
                #pragma unroll
                for (int ni = 0; ni < 4; ni++) {
                    mma16816(acc[mi][ni], ah[mi][0], ah[mi][1], ah[mi][2], ah[mi][3], bh[ni][0], bh[ni][1]);
                    mma16816(acc[mi][ni], ah[mi][0], ah[mi][1], ah[mi][2], ah[mi][3], bl[ni][0], bl[ni][1]);
                    mma16816(acc[mi][ni], al[mi][0], al[mi][1], al[mi][2], al[mi][3], bh[ni][0], bh[ni][1]);
                }
        }
        __syncthreads();
    }

    // epilogue
    #pragma unroll
    for (int mi = 0; mi < 2; mi++) {
        #pragma unroll
        for (int ni = 0; ni < 4; ni++) {
            int col = block_n + warp_n * 32 + ni * 8 + tg * 2;
            float bx = bias[col], by = bias[col + 1];
            int row0 = block_m + warp_m * 32 + mi * 16 + g;
            #pragma unroll
            for (int h = 0; h < 2; h++) {
                int row = row0 + h * 8;
                if (row < N_NODES) {
                    float vx = acc[mi][ni][h * 2 + 0] + bx;
                    float vy = acc[mi][ni][h * 2 + 1] + by;
                    if (RELU) { vx = fmaxf(vx, 0.f); vy = fmaxf(vy, 0.f); }
                    float2 o = {vx, vy};
                    *(float2*)&C[(size_t)row * DO + col] = o;
                }
            }
        }
    }
}

extern "C" void kernel_launch(void* const* d_in, const int* in_sizes, int n_in,
                              void* d_out, int out_size) {
    const float* x   = (const float*)d_in[0];
    const int*   ei  = (const int*)d_in[1];     // int32 (harness converts int64)
    const float* Wl0 = (const float*)d_in[2];
    const float* bl0 = (const float*)d_in[3];
    const float* Wr0 = (const float*)d_in[4];
    const float* Wl1 = (const float*)d_in[5];
    const float* bl1 = (const float*)d_in[6];
    const float* Wr1 = (const float*)d_in[7];
    const float* Wl2 = (const float*)d_in[8];
    const float* bl2 = (const float*)d_in[9];
    const float* Wr2 = (const float*)d_in[10];
    float* out = (float*)d_out;

    const int SMEM = 2 * BUF_ELEMS * 2;   // 147456 B
    cudaFuncSetAttribute(k_gemm_db<128, true>,  cudaFuncAttributeMaxDynamicSharedMemorySize, SMEM);
    cudaFuncSetAttribute(k_gemm_db<256, false>, cudaFuncAttributeMaxDynamicSharedMemorySize, SMEM);

    // --- CSR build + weight prep (merged count+prep: one fewer launch) ---
    k_zero_deg<<<(N_NODES + 255) / 256, 256>>>();
    k_count_prep<<<COUNT_BLOCKS + PREP_BLOCKS, 256>>>(ei, Wl0, Wr0, Wl1, Wr1, Wl2, Wr2);
    k_scan_part<<<SCAN_BLOCKS, 1024>>>();
    k_scan_add<<<SCAN_BLOCKS, 1024>>>();
    k_fill<<<(E_EDGES + 255) / 256, 256>>>(ei);

    const int GRID_M = (N_NODES + 127) / 128;   // 391

    // --- layer 0: x -> g_h0 (relu) ---
    k_agg<<<(N_NODES + 7) / 8, 256>>>(x, 0);
    k_gemm_db<128, true><<<dim3(GRID_M, 1), 512, SMEM>>>(bl0, nullptr, 0, 0);

    // --- layer 1: g_h0 -> g_h1 (relu) ---
    k_agg<<<(N_NODES + 7) / 8, 256>>>(nullptr, 1);
    k_gemm_db<128, true><<<dim3(GRID_M, 1), 512, SMEM>>>(bl1, nullptr, 1, 1);

    // --- layer 2: g_h1 -> out (no relu) ---
    k_agg<<<(N_NODES + 7) / 8, 256>>>(nullptr, 2);
    k_gemm_db<256, false><<<dim3(GRID_M, 2), 512, SMEM>>>(bl2, out, 2, 2);
}